// round 11
// baseline (speedup 1.0000x reference)
#include <cuda_runtime.h>

#define NDET    8192
#define ROW     85
#define IMG     640
#define CAP     128          // fast-path capacity (V ~ 77 expected)
#define W32     4            // 128/32 words per suppression row
#define NBLK    128
#define NTHR    1024
#define ZPB     320          // output floats zeroed per block (128*320 = 40960)

// Global scratch (allocation-free rule). g_cnt/g_done zero at module load,
// reset by the NMS block every launch -> deterministic across graph replays.
__device__ int    g_cnt  = 0;
__device__ int    g_done = 0;
__device__ float  c_conf[NDET];
__device__ float4 c_box[NDET];
__device__ int    c_idx[NDET];
// slow-path (V > CAP) scratch only:
__device__ float  s_conf[NDET];
__device__ float4 s_box[NDET];

// ---------------------------------------------------------------------------
// Fused kernel: 128 blocks x 1024 threads = 1 block/SM, one balanced wave.
// Phase A: each block zeroes its 320-float out slice (balanced); each warp
//   decodes 2 detections with batched loads; class max via __reduce_max_sync
//   (exact: scores are non-negative fp32); valid dets compacted via atomicAdd.
// Phase B (last arriving block): concurrent entry loads, stable rank sort,
//   ballot suppression bitmatrix with low-word skip, ffs-driven register
//   greedy (alive-only iterations), scatter.
// ---------------------------------------------------------------------------
__global__ void __launch_bounds__(NTHR) yolo_fused(const float* __restrict__ x,
                                                   float* __restrict__ out) {
    const int t    = threadIdx.x;
    const int lane = t & 31;
    const int wid  = t >> 5;

    __shared__ float sx1[CAP], sy1[CAP], sx2[CAP], sy2[CAP], scf[CAP];
    __shared__ unsigned long long skey[CAP];
    __shared__ unsigned int sup[2048];   // fast: CAP*W32=512 used; slow: 8KB keep[]
    __shared__ unsigned int keepw[W32];
    __shared__ int sh_last;

    // ================= Phase A =================
    if (t < ZPB) out[blockIdx.x * ZPB + t] = 0.0f;   // balanced zeroing

    {
        int det0 = blockIdx.x * 64 + wid;
        int det1 = det0 + 32;
        const float* r0 = x + (long)det0 * ROW;
        const float* r1 = x + (long)det1 * ROW;
        // batch all 6 independent loads (MLP = 6 per warp)
        float a0 = r0[lane];
        float a1 = r0[lane + 32];
        float a2 = (lane < 21) ? r0[lane + 64] : 0.0f;
        float e0 = r1[lane];
        float e1 = r1[lane + 32];
        float e2 = (lane < 21) ? r1[lane + 64] : 0.0f;

        // class max over positions 6..84; scores are uniform[0,1) >= 0 so
        // uint order == float order and 0.0f is a safe identity.
        float ma = (lane >= 6) ? a0 : 0.0f;
        ma = fmaxf(ma, a1); ma = fmaxf(ma, a2);
        float me = (lane >= 6) ? e0 : 0.0f;
        me = fmaxf(me, e1); me = fmaxf(me, e2);
        unsigned int mA = __reduce_max_sync(0xffffffffu, __float_as_uint(ma));
        unsigned int mE = __reduce_max_sync(0xffffffffu, __float_as_uint(me));

        #pragma unroll
        for (int pass = 0; pass < 2; pass++) {
            float src  = pass ? e0 : a0;
            float b0   = __shfl_sync(0xffffffffu, src, 0);
            float b1   = __shfl_sync(0xffffffffu, src, 1);
            float b2   = __shfl_sync(0xffffffffu, src, 2);
            float b3   = __shfl_sync(0xffffffffu, src, 3);
            float conf = __shfl_sync(0xffffffffu, src, 4);
            float cls0 = __shfl_sync(0xffffffffu, src, 5);
            if (lane == 0) {
                float m = __uint_as_float(pass ? mE : mA);
                int det  = pass ? det1 : det0;
                float cx = b0 * 640.0f, cy = b1 * 640.0f;
                float w  = b2 * 640.0f, h  = b3 * 640.0f;
                // argmax==0 <=> cls0 >= max(later classes)
                if ((conf > 0.25f) && (cls0 >= m) &&
                    ((w > 0.0f) || (h > 0.0f))) {
                    float hw = truncf(w * 0.5f);
                    float hh = truncf(h * 0.5f);
                    int x1 = (int)(cx - hw);
                    int y1 = (int)(cy - hh);
                    int x2 = (int)(cx + hw);
                    int y2 = (int)(cy + hh);
                    x1 = x1 > 0 ? x1 : 0;
                    y1 = y1 > 0 ? y1 : 0;
                    x2 = x2 < IMG ? x2 : IMG;
                    y2 = y2 < IMG ? y2 : IMG;
                    int slot = atomicAdd(&g_cnt, 1);
                    c_conf[slot] = conf;
                    c_idx[slot]  = det;
                    c_box[slot]  = make_float4((float)x1, (float)y1,
                                               (float)x2, (float)y2);
                }
            }
        }
    }

    // ---- completion handshake: last finished block runs NMS ----
    __syncthreads();
    __threadfence();
    if (t == 0) {
        int prev = atomicAdd(&g_done, 1);
        sh_last = (prev == NBLK - 1);
    }
    __syncthreads();
    if (!sh_last) return;
    __threadfence();            // acquire: see all blocks' writes

    // ================= Phase B: NMS (single block) =================
    // Concurrent entry loads (single L2 round trip); lanes t >= V read
    // stale-but-masked data: every use below is guarded by t < V.
    float mcf = 0, mx1 = 0, my1 = 0, mx2 = 0, my2 = 0;
    int   midx = 0;
    if (t < CAP) {
        float4 b = c_box[t];
        mcf  = c_conf[t];
        midx = c_idx[t];
        mx1 = b.x; my1 = b.y; mx2 = b.z; my2 = b.w;
    }
    const int V = g_cnt;

    if (V <= CAP) {
        unsigned long long mykey = 0;
        if (t < V) {
            mykey = ((unsigned long long)__float_as_uint(mcf) << 32)
                  | (unsigned int)(~midx);
            skey[t] = mykey;
        }
        __syncthreads();

        // ---- rank sort (stable: conf desc, original idx asc) ----
        if (t < V) {
            int r = 0;
            int j = 0;
            for (; j + 4 <= V; j += 4) {
                r += (skey[j]     > mykey);
                r += (skey[j + 1] > mykey);
                r += (skey[j + 2] > mykey);
                r += (skey[j + 3] > mykey);
            }
            for (; j < V; j++) r += (skey[j] > mykey);
            sx1[r] = mx1; sy1[r] = my1; sx2[r] = mx2; sy2[r] = my2; scf[r] = mcf;
        }
        __syncthreads();

        // ---- suppression matrix: warp per row; skip words left of diag ----
        const int nw = (V + 31) >> 5;
        for (int i = wid; i < V; i += 32) {
            float x1i = sx1[i], y1i = sy1[i], x2i = sx2[i], y2i = sy2[i];
            float areai = (x2i - x1i) * (y2i - y1i);   // exact in fp32
            int wlow = i >> 5;
            for (int b = 0; b < nw; b++) {
                if (b < wlow) {
                    if (lane == 0) sup[i * W32 + b] = 0u;   // no ballot/IoU
                    continue;
                }
                int j = (b << 5) + lane;
                bool sb = false;
                if (j > i && j < V) {
                    float x1j = sx1[j], y1j = sy1[j];
                    float x2j = sx2[j], y2j = sy2[j];
                    float iw = fmaxf(fminf(x2i, x2j) - fmaxf(x1i, x1j), 0.0f);
                    float ih = fmaxf(fminf(y2i, y2j) - fmaxf(y1i, y1j), 0.0f);
                    float inter = iw * ih;
                    float areaj = (x2j - x1j) * (y2j - y1j);
                    float uni = areai + areaj - inter;
                    float iou = __fdiv_rn(inter, fmaxf(uni, 1e-9f)); // IEEE
                    sb = iou > 0.45f;
                }
                unsigned int bits = __ballot_sync(0xffffffffu, sb);
                if (lane == 0) sup[i * W32 + b] = bits;
            }
            // zero any unused high words so greedy can read all 4 blindly
            for (int b = nw; b < W32; b++)
                if (lane == 0) sup[i * W32 + b] = 0u;
        }
        __syncthreads();

        // ---- ffs-driven greedy: iterate alive boxes only, kw in registers ----
        if (t == 0) {
            unsigned int kw0 = 0xFFFFFFFFu, kw1 = 0xFFFFFFFFu;
            unsigned int kw2 = 0xFFFFFFFFu, kw3 = 0xFFFFFFFFu;
            #pragma unroll
            for (int w = 0; w < W32; w++) {
                int base = w << 5;
                int rem  = V - base;
                if (rem <= 0) break;
                unsigned int vm = (rem >= 32) ? 0xFFFFFFFFu
                                              : ((1u << rem) - 1u);
                unsigned int cur = (w == 0 ? kw0 : w == 1 ? kw1
                                   : w == 2 ? kw2 : kw3);
                unsigned int live = cur & vm;
                while (live) {
                    int b = __ffs(live) - 1;
                    int i = base + b;
                    // box i is kept; suppress everything it overlaps
                    kw0 &= ~sup[i * W32 + 0];
                    kw1 &= ~sup[i * W32 + 1];
                    kw2 &= ~sup[i * W32 + 2];
                    kw3 &= ~sup[i * W32 + 3];
                    // note: row i never suppresses j <= i, so bit b survives
                    unsigned int upd = (w == 0 ? kw0 : w == 1 ? kw1
                                        : w == 2 ? kw2 : kw3);
                    live &= (live - 1);          // consume bit b
                    live &= upd;                 // drop newly suppressed
                }
            }
            keepw[0] = kw0; keepw[1] = kw1; keepw[2] = kw2; keepw[3] = kw3;
        }
        __syncthreads();

        // ---- scatter survivors (rest of out zeroed in Phase A) ----
        if (t < V && ((keepw[t >> 5] >> (t & 31)) & 1u)) {
            out[4 * t + 0] = sx1[t];
            out[4 * t + 1] = sy1[t];
            out[4 * t + 2] = sx2[t];
            out[4 * t + 3] = sy2[t];
            out[NDET * 4 + t] = scf[t];
        }
        if (t == 0) { g_cnt = 0; g_done = 0; }   // reset for next replay
    } else {
        // ============ SLOW PATH (V > CAP; global arrays) ============
        for (int i = t; i < V; i += NTHR) {
            float ci = c_conf[i];
            int  ii  = c_idx[i];
            int r = 0;
            for (int j = 0; j < V; j++) {
                float cj = c_conf[j];
                r += (cj > ci) || (cj == ci && c_idx[j] < ii);
            }
            s_conf[r] = ci;
            s_box[r]  = c_box[i];
        }
        __syncthreads();

        unsigned char* keep = (unsigned char*)&sup[0];   // 8KB == NDET bytes
        for (int i = t; i < NDET; i += NTHR) keep[i] = 1;
        __syncthreads();
        for (int i = 0; i + 1 < V; i++) {
            if (keep[i]) {
                float4 bi = s_box[i];
                float areai = (bi.z - bi.x) * (bi.w - bi.y);
                for (int j = i + 1 + t; j < V; j += NTHR) {
                    if (keep[j]) {
                        float4 bj = s_box[j];
                        float iw = fmaxf(fminf(bi.z, bj.z) - fmaxf(bi.x, bj.x), 0.0f);
                        float ih = fmaxf(fminf(bi.w, bj.w) - fmaxf(bi.y, bj.y), 0.0f);
                        float inter = iw * ih;
                        float areaj = (bj.z - bj.x) * (bj.w - bj.y);
                        float uni = areai + areaj - inter;
                        float iou = __fdiv_rn(inter, fmaxf(uni, 1e-9f));
                        if (iou > 0.45f) keep[j] = 0;
                    }
                }
            }
            __syncthreads();
        }
        for (int i = t; i < V; i += NTHR) {
            if (keep[i]) {
                float4 b = s_box[i];
                out[4 * i + 0] = b.x;
                out[4 * i + 1] = b.y;
                out[4 * i + 2] = b.z;
                out[4 * i + 3] = b.w;
                out[NDET * 4 + i] = s_conf[i];
            }
        }
        if (t == 0) { g_cnt = 0; g_done = 0; }
    }
}

extern "C" void kernel_launch(void* const* d_in, const int* in_sizes, int n_in,
                              void* d_out, int out_size) {
    const float* x = (const float*)d_in[0];   // (1, 8192, 85) fp32
    float* out = (float*)d_out;               // 8192*4 boxes then 8192 scores
    yolo_fused<<<NBLK, NTHR>>>(x, out);
}

// round 12
// speedup vs baseline: 1.2470x; 1.2470x over previous
#include <cuda_runtime.h>

#define NDET    8192
#define ROW     85
#define IMG     640
#define CAP     128          // fast-path capacity (V ~ 77 expected)
#define W32     4            // 128/32 words per row
#define NBLK    128
#define NTHR    1024
#define ZPB     320          // output floats zeroed per block (128*320 = 40960)

// Global scratch (allocation-free rule). g_cnt/g_done zero at module load,
// reset by the NMS block every launch -> deterministic across graph replays.
__device__ int    g_cnt  = 0;
__device__ int    g_done = 0;
__device__ float  c_conf[NDET];
__device__ float4 c_box[NDET];
__device__ int    c_idx[NDET];
// slow-path (V > CAP) scratch only:
__device__ float  s_conf[NDET];
__device__ float4 s_box[NDET];

// ---------------------------------------------------------------------------
// Fused kernel: 128 blocks x 1024 threads = 1 block/SM, one balanced wave.
// Phase A: balanced output zeroing; each warp decodes 2 detections (batched
//   loads, __reduce_max_sync class max — exact for non-negative fp32); valid
//   dets compacted via atomicAdd.
// Phase B (last arriving block): concurrent entry loads, stable rank sort,
//   TRANSPOSED ballot suppression matrix (row j = suppressors of j), then a
//   warp-0 Jacobi fixpoint (register-only carry chain; unique fixpoint ==
//   sequential greedy NMS since sup is strictly triangular), scatter.
// ---------------------------------------------------------------------------
__global__ void __launch_bounds__(NTHR) yolo_fused(const float* __restrict__ x,
                                                   float* __restrict__ out) {
    const int t    = threadIdx.x;
    const int lane = t & 31;
    const int wid  = t >> 5;

    __shared__ float sx1[CAP], sy1[CAP], sx2[CAP], sy2[CAP], scf[CAP];
    __shared__ unsigned long long skey[CAP];
    __shared__ unsigned int supT[CAP * W32];   // fast path: 2 KB (row j = suppressors)
    __shared__ unsigned char keep8[NDET];      // slow path only (8 KB)
    __shared__ int sh_last;

    // ================= Phase A =================
    if (t < ZPB) out[blockIdx.x * ZPB + t] = 0.0f;   // balanced zeroing

    {
        int det0 = blockIdx.x * 64 + wid;
        int det1 = det0 + 32;
        const float* r0 = x + (long)det0 * ROW;
        const float* r1 = x + (long)det1 * ROW;
        // batch all 6 independent loads (MLP = 6 per warp)
        float a0 = r0[lane];
        float a1 = r0[lane + 32];
        float a2 = (lane < 21) ? r0[lane + 64] : 0.0f;
        float e0 = r1[lane];
        float e1 = r1[lane + 32];
        float e2 = (lane < 21) ? r1[lane + 64] : 0.0f;

        // class max over positions 6..84; scores are uniform[0,1) >= 0 so
        // uint order == float order and 0.0f is a safe identity.
        float ma = (lane >= 6) ? a0 : 0.0f;
        ma = fmaxf(ma, a1); ma = fmaxf(ma, a2);
        float me = (lane >= 6) ? e0 : 0.0f;
        me = fmaxf(me, e1); me = fmaxf(me, e2);
        unsigned int mA = __reduce_max_sync(0xffffffffu, __float_as_uint(ma));
        unsigned int mE = __reduce_max_sync(0xffffffffu, __float_as_uint(me));

        #pragma unroll
        for (int pass = 0; pass < 2; pass++) {
            float src  = pass ? e0 : a0;
            float b0   = __shfl_sync(0xffffffffu, src, 0);
            float b1   = __shfl_sync(0xffffffffu, src, 1);
            float b2   = __shfl_sync(0xffffffffu, src, 2);
            float b3   = __shfl_sync(0xffffffffu, src, 3);
            float conf = __shfl_sync(0xffffffffu, src, 4);
            float cls0 = __shfl_sync(0xffffffffu, src, 5);
            if (lane == 0) {
                float m = __uint_as_float(pass ? mE : mA);
                int det  = pass ? det1 : det0;
                float cx = b0 * 640.0f, cy = b1 * 640.0f;
                float w  = b2 * 640.0f, h  = b3 * 640.0f;
                // argmax==0 <=> cls0 >= max(later classes)
                if ((conf > 0.25f) && (cls0 >= m) &&
                    ((w > 0.0f) || (h > 0.0f))) {
                    float hw = truncf(w * 0.5f);
                    float hh = truncf(h * 0.5f);
                    int x1 = (int)(cx - hw);
                    int y1 = (int)(cy - hh);
                    int x2 = (int)(cx + hw);
                    int y2 = (int)(cy + hh);
                    x1 = x1 > 0 ? x1 : 0;
                    y1 = y1 > 0 ? y1 : 0;
                    x2 = x2 < IMG ? x2 : IMG;
                    y2 = y2 < IMG ? y2 : IMG;
                    int slot = atomicAdd(&g_cnt, 1);
                    c_conf[slot] = conf;
                    c_idx[slot]  = det;
                    c_box[slot]  = make_float4((float)x1, (float)y1,
                                               (float)x2, (float)y2);
                }
            }
        }
    }

    // ---- completion handshake: last finished block runs NMS ----
    __syncthreads();
    __threadfence();
    if (t == 0) {
        int prev = atomicAdd(&g_done, 1);
        sh_last = (prev == NBLK - 1);
    }
    __syncthreads();
    if (!sh_last) return;
    __threadfence();            // acquire: see all blocks' writes

    // ================= Phase B: NMS (single block) =================
    // Concurrent entry loads; lanes t >= V read stale-but-masked data.
    float mcf = 0, mx1 = 0, my1 = 0, mx2 = 0, my2 = 0;
    int   midx = 0;
    if (t < CAP) {
        float4 b = c_box[t];
        mcf  = c_conf[t];
        midx = c_idx[t];
        mx1 = b.x; my1 = b.y; mx2 = b.z; my2 = b.w;
    }
    if (t < CAP * W32) supT[t] = 0u;            // zero matrix upfront
    const int V = g_cnt;

    if (V <= CAP) {
        unsigned long long mykey = 0;
        if (t < V) {
            mykey = ((unsigned long long)__float_as_uint(mcf) << 32)
                  | (unsigned int)(~midx);
            skey[t] = mykey;
        }
        __syncthreads();

        // ---- rank sort (stable: conf desc, original idx asc) ----
        if (t < V) {
            int r = 0;
            int j = 0;
            for (; j + 4 <= V; j += 4) {
                r += (skey[j]     > mykey);
                r += (skey[j + 1] > mykey);
                r += (skey[j + 2] > mykey);
                r += (skey[j + 3] > mykey);
            }
            for (; j < V; j++) r += (skey[j] > mykey);
            sx1[r] = mx1; sy1[r] = my1; sx2[r] = mx2; sy2[r] = my2; scf[r] = mcf;
        }
        __syncthreads();

        // ---- TRANSPOSED suppression matrix: warp handles row j; lane = i.
        //      bit i of supT[j][w] set iff i < j and iou(i,j) > thres.
        //      Only words w <= j>>5 can have bits; rest stay zero. ----
        for (int j = wid; j < V; j += 32) {
            float x1j = sx1[j], y1j = sy1[j], x2j = sx2[j], y2j = sy2[j];
            float areaj = (x2j - x1j) * (y2j - y1j);   // exact in fp32
            int wmax = j >> 5;
            for (int w = 0; w <= wmax; w++) {
                int i = (w << 5) + lane;
                bool sb = false;
                if (i < j) {
                    float x1i = sx1[i], y1i = sy1[i];
                    float x2i = sx2[i], y2i = sy2[i];
                    float iw = fmaxf(fminf(x2i, x2j) - fmaxf(x1i, x1j), 0.0f);
                    float ih = fmaxf(fminf(y2i, y2j) - fmaxf(y1i, y1j), 0.0f);
                    float inter = iw * ih;
                    float areai = (x2i - x1i) * (y2i - y1i);
                    float uni = areai + areaj - inter;
                    float iou = __fdiv_rn(inter, fmaxf(uni, 1e-9f)); // IEEE
                    sb = iou > 0.45f;
                }
                unsigned int bits = __ballot_sync(0xffffffffu, sb);
                if (lane == 0) supT[j * W32 + w] = bits;
            }
        }
        __syncthreads();

        // ---- warp-0 Jacobi fixpoint (== greedy NMS, unique fixpoint) ----
        if (wid == 0) {
            // lane owns j in {lane, lane+32, lane+64, lane+96}
            unsigned int rT[W32][W32];           // this lane's 4 rows
            #pragma unroll
            for (int k = 0; k < W32; k++) {
                int j = (k << 5) + lane;
                #pragma unroll
                for (int w = 0; w < W32; w++)
                    rT[k][w] = (j < V) ? supT[j * W32 + w] : 0u;
            }
            unsigned int kw[W32];                // alive mask (uniform)
            #pragma unroll
            for (int w = 0; w < W32; w++) {
                int rem = V - (w << 5);
                kw[w] = (rem >= 32) ? 0xFFFFFFFFu
                      : (rem <= 0)  ? 0u : ((1u << rem) - 1u);
            }
            for (int it = 0; it < CAP; it++) {   // expected ~3 iterations
                unsigned int nkw[W32];
                #pragma unroll
                for (int k = 0; k < W32; k++) {
                    int j = (k << 5) + lane;
                    unsigned int dead = (rT[k][0] & kw[0]) | (rT[k][1] & kw[1])
                                      | (rT[k][2] & kw[2]) | (rT[k][3] & kw[3]);
                    bool alive = (j < V) && (dead == 0u);
                    nkw[k] = __ballot_sync(0xffffffffu, alive);
                }
                unsigned int changed = 0u;       // uniform across lanes
                #pragma unroll
                for (int k = 0; k < W32; k++) {
                    changed |= nkw[k] ^ kw[k];
                    kw[k] = nkw[k];
                }
                if (changed == 0u) break;        // fixpoint == greedy result
            }
            // ---- scatter survivors (rest of out zeroed in Phase A) ----
            #pragma unroll
            for (int k = 0; k < W32; k++) {
                int j = (k << 5) + lane;
                if (j < V && ((kw[k] >> lane) & 1u)) {
                    out[4 * j + 0] = sx1[j];
                    out[4 * j + 1] = sy1[j];
                    out[4 * j + 2] = sx2[j];
                    out[4 * j + 3] = sy2[j];
                    out[NDET * 4 + j] = scf[j];
                }
            }
            if (lane == 0) { g_cnt = 0; g_done = 0; }   // reset for replay
        }
        // other warps exit; no trailing barrier needed
    } else {
        // ============ SLOW PATH (V > CAP; global arrays) ============
        __syncthreads();
        for (int i = t; i < V; i += NTHR) {
            float ci = c_conf[i];
            int  ii  = c_idx[i];
            int r = 0;
            for (int j = 0; j < V; j++) {
                float cj = c_conf[j];
                r += (cj > ci) || (cj == ci && c_idx[j] < ii);
            }
            s_conf[r] = ci;
            s_box[r]  = c_box[i];
        }
        __syncthreads();

        for (int i = t; i < NDET; i += NTHR) keep8[i] = 1;
        __syncthreads();
        for (int i = 0; i + 1 < V; i++) {
            if (keep8[i]) {
                float4 bi = s_box[i];
                float areai = (bi.z - bi.x) * (bi.w - bi.y);
                for (int j = i + 1 + t; j < V; j += NTHR) {
                    if (keep8[j]) {
                        float4 bj = s_box[j];
                        float iw = fmaxf(fminf(bi.z, bj.z) - fmaxf(bi.x, bj.x), 0.0f);
                        float ih = fmaxf(fminf(bi.w, bj.w) - fmaxf(bi.y, bj.y), 0.0f);
                        float inter = iw * ih;
                        float areaj = (bj.z - bj.x) * (bj.w - bj.y);
                        float uni = areai + areaj - inter;
                        float iou = __fdiv_rn(inter, fmaxf(uni, 1e-9f));
                        if (iou > 0.45f) keep8[j] = 0;
                    }
                }
            }
            __syncthreads();
        }
        for (int i = t; i < V; i += NTHR) {
            if (keep8[i]) {
                float4 b = s_box[i];
                out[4 * i + 0] = b.x;
                out[4 * i + 1] = b.y;
                out[4 * i + 2] = b.z;
                out[4 * i + 3] = b.w;
                out[NDET * 4 + i] = s_conf[i];
            }
        }
        if (t == 0) { g_cnt = 0; g_done = 0; }
    }
}

extern "C" void kernel_launch(void* const* d_in, const int* in_sizes, int n_in,
                              void* d_out, int out_size) {
    const float* x = (const float*)d_in[0];   // (1, 8192, 85) fp32
    float* out = (float*)d_out;               // 8192*4 boxes then 8192 scores
    yolo_fused<<<NBLK, NTHR>>>(x, out);
}